// round 1
// baseline (speedup 1.0000x reference)
#include <cuda_runtime.h>
#include <cuda_fp16.h>
#include <cstdint>

// ---------------- problem constants ----------------
#define T_TOK   2048      // B*S tokens
#define DDIM    1024
#define EXP     8
#define HDIM    4096
#define ROUTED_CAP  5120  // 4096 selections + per-expert 128-alignment padding
#define SHARED_BASE 5120
#define TOTAL_ROWS  7168  // ROUTED_CAP + 2048 shared rows
#define NTILES      56    // TOTAL_ROWS / 128
#define ROUTED_TILES 40   // ROUTED_CAP / 128

// ---------------- device scratch (static: no allocs allowed) ----------------
__device__ int   g_cnt[EXP];
__device__ int   g_fill[EXP];
__device__ int   g_segstart[EXP];
__device__ int   g_tile_expert[NTILES];
__device__ int   g_row_token[TOTAL_ROWS];
__device__ int   g_top_idx[T_TOK * 2];
__device__ float g_top_w[T_TOK * 2];
__device__ int   g_slot[T_TOK * 2];
__device__ __align__(16) __half g_h[(size_t)TOTAL_ROWS * HDIM];   // ~58.7 MB
__device__ __align__(16) float  g_eo[(size_t)TOTAL_ROWS * DDIM];  // ~29.4 MB

// ---------------- helpers ----------------
__device__ __forceinline__ float gelu_exact(float v) {
    return 0.5f * v * (1.0f + erff(v * 0.70710678118654752f));
}

__device__ __forceinline__ void sts4h(__half* dst, float4 v) {
    __half2 p0 = __floats2half2_rn(v.x, v.y);
    __half2 p1 = __floats2half2_rn(v.z, v.w);
    uint2 u;
    u.x = *reinterpret_cast<uint32_t*>(&p0);
    u.y = *reinterpret_cast<uint32_t*>(&p1);
    *reinterpret_cast<uint2*>(dst) = u;
}

__device__ __forceinline__ void ldsm_x4(uint32_t* r, const void* p) {
    uint32_t a = (uint32_t)__cvta_generic_to_shared(p);
    asm volatile("ldmatrix.sync.aligned.m8n8.x4.shared.b16 {%0,%1,%2,%3}, [%4];\n"
                 : "=r"(r[0]), "=r"(r[1]), "=r"(r[2]), "=r"(r[3]) : "r"(a));
}

__device__ __forceinline__ void mma16816(float* c, const uint32_t* a, const uint32_t* b) {
    asm volatile(
        "mma.sync.aligned.m16n8k16.row.col.f32.f16.f16.f32 "
        "{%0,%1,%2,%3}, {%4,%5,%6,%7}, {%8,%9}, {%0,%1,%2,%3};\n"
        : "+f"(c[0]), "+f"(c[1]), "+f"(c[2]), "+f"(c[3])
        : "r"(a[0]), "r"(a[1]), "r"(a[2]), "r"(a[3]), "r"(b[0]), "r"(b[1]));
}

// ---------------- routing kernels ----------------
__global__ void k_init() {
    int i = blockIdx.x * blockDim.x + threadIdx.x;
    if (i < TOTAL_ROWS)
        g_row_token[i] = (i >= SHARED_BASE) ? (i - SHARED_BASE) : -1;
    if (i < EXP) { g_cnt[i] = 0; g_fill[i] = 0; }
}

__global__ void k_gate(const float* __restrict__ x, const float* __restrict__ Wg,
                       const float* __restrict__ bg, const float* __restrict__ bias) {
    int gwarp = (blockIdx.x * blockDim.x + threadIdx.x) >> 5;
    int lane  = threadIdx.x & 31;
    if (gwarp >= T_TOK) return;
    const float* xr = x + (size_t)gwarp * DDIM;
    float xs[32];
#pragma unroll
    for (int j = 0; j < 32; j++) xs[j] = xr[lane + 32 * j];
    float s[EXP];
#pragma unroll
    for (int e = 0; e < EXP; e++) {
        const float* wr = Wg + e * DDIM;
        float a = 0.f;
#pragma unroll
        for (int j = 0; j < 32; j++) a += xs[j] * wr[lane + 32 * j];
#pragma unroll
        for (int o = 16; o > 0; o >>= 1) a += __shfl_xor_sync(0xffffffffu, a, o);
        s[e] = 1.0f / (1.0f + expf(-(a + bg[e] + bias[e])));
    }
    if (lane == 0) {
        int i0 = 0; float v0 = s[0];
#pragma unroll
        for (int e = 1; e < EXP; e++) if (s[e] > v0) { v0 = s[e]; i0 = e; }
        int i1 = -1; float v1 = -1e30f;
#pragma unroll
        for (int e = 0; e < EXP; e++) if (e != i0 && s[e] > v1) { v1 = s[e]; i1 = e; }
        g_top_idx[2 * gwarp]     = i0; g_top_w[2 * gwarp]     = v0;
        g_top_idx[2 * gwarp + 1] = i1; g_top_w[2 * gwarp + 1] = v1;
        atomicAdd(&g_cnt[i0], 1);
        atomicAdd(&g_cnt[i1], 1);
    }
}

__global__ void k_seg() {
    if (threadIdx.x == 0 && blockIdx.x == 0) {
        int off = 0;
        for (int e = 0; e < EXP; e++) {
            g_segstart[e] = off;
            int tiles = (g_cnt[e] + 127) >> 7;
            for (int i = 0; i < tiles; i++) g_tile_expert[(off >> 7) + i] = e;
            off += tiles * 128;
        }
        for (int t = off >> 7; t < ROUTED_TILES; t++) g_tile_expert[t] = -1;
        for (int t = ROUTED_TILES; t < NTILES; t++)   g_tile_expert[t] = EXP; // shared
    }
}

__global__ void k_scatter() {
    int t = blockIdx.x * blockDim.x + threadIdx.x;
    if (t >= T_TOK) return;
#pragma unroll
    for (int k = 0; k < 2; k++) {
        int e = g_top_idx[2 * t + k];
        int pos = atomicAdd(&g_fill[e], 1);
        int row = g_segstart[e] + pos;
        g_slot[2 * t + k] = row;
        g_row_token[row]  = t;
    }
}

// ---------------- GEMM1: h = gelu(x_gather @ W1[e]^T + b1[e]) -> fp16 ----------------
// M=128/tile (gathered tokens), N=HDIM, K=DDIM.  A fp32 gathered, B fp32 [H,D].
__global__ __launch_bounds__(256) void k_gemm1(
    const float* __restrict__ x,  const float* __restrict__ W1, const float* __restrict__ b1,
    const float* __restrict__ Ws1, const float* __restrict__ bs1) {
    __shared__ __half sA[2][128][40];
    __shared__ __half sB[2][128][40];

    int ty = blockIdx.y;
    int e  = g_tile_expert[ty];
    if (e < 0) return;
    const float* Bsrc; const float* bias;
    if (e == EXP) { Bsrc = Ws1; bias = bs1; }
    else          { Bsrc = W1 + (size_t)e * HDIM * DDIM; bias = b1 + (size_t)e * HDIM; }

    int row0 = ty * 128, col0 = blockIdx.x * 128;
    int tid = threadIdx.x, lane = tid & 31, warp = tid >> 5;
    int wm = warp >> 2, wn = warp & 3;

    // Staging slots: 4 float4 for A, 4 float4 for B (128x32 fp32 each)
    const float* abase[4]; bool aval[4]; int arow[4], acol[4];
    const float* bbase[4]; int brow[4], bcol[4];
#pragma unroll
    for (int i = 0; i < 4; i++) {
        int lin = tid + i * 256;            // 0..1023
        int r = lin >> 3, c4 = lin & 7;     // r:0..127 c4:0..7
        arow[i] = r; acol[i] = c4 * 4;
        int tok = g_row_token[row0 + r];
        aval[i] = (tok >= 0);
        abase[i] = aval[i] ? (x + (size_t)tok * DDIM + c4 * 4) : x;
        brow[i] = r; bcol[i] = c4 * 4;
        bbase[i] = Bsrc + (size_t)(col0 + r) * DDIM + c4 * 4;
    }

    float4 ar[4], br[4];
#pragma unroll
    for (int i = 0; i < 4; i++) {
        ar[i] = aval[i] ? *reinterpret_cast<const float4*>(abase[i]) : make_float4(0,0,0,0);
        br[i] = *reinterpret_cast<const float4*>(bbase[i]);
    }
#pragma unroll
    for (int i = 0; i < 4; i++) {
        sts4h(&sA[0][arow[i]][acol[i]], ar[i]);
        sts4h(&sB[0][brow[i]][bcol[i]], br[i]);
    }
    __syncthreads();

    float acc[4][4][4];
#pragma unroll
    for (int mi = 0; mi < 4; mi++)
#pragma unroll
        for (int ni = 0; ni < 4; ni++)
#pragma unroll
            for (int j = 0; j < 4; j++) acc[mi][ni][j] = 0.f;

    int buf = 0;
    for (int kk = 0; kk < DDIM; kk += 32) {
        int nk = kk + 32;
        bool more = (nk < DDIM);
        if (more) {
#pragma unroll
            for (int i = 0; i < 4; i++) {
                ar[i] = aval[i] ? *reinterpret_cast<const float4*>(abase[i] + nk)
                                : make_float4(0,0,0,0);
                br[i] = *reinterpret_cast<const float4*>(bbase[i] + nk);
            }
        }
#pragma unroll
        for (int ks = 0; ks < 32; ks += 16) {
            uint32_t af[4][4], bf[4][2];
#pragma unroll
            for (int mi = 0; mi < 4; mi++) {
                int r = wm * 64 + mi * 16 + ((lane >> 3) & 1) * 8 + (lane & 7);
                int c = ks + (lane >> 4) * 8;
                ldsm_x4(af[mi], &sA[buf][r][c]);
            }
#pragma unroll
            for (int np = 0; np < 2; np++) {
                int r = wn * 32 + np * 16 + (lane >> 4) * 8 + (lane & 7);
                int c = ks + ((lane >> 3) & 1) * 8;
                uint32_t t4[4];
                ldsm_x4(t4, &sB[buf][r][c]);
                bf[np * 2][0] = t4[0]; bf[np * 2][1] = t4[1];
                bf[np * 2 + 1][0] = t4[2]; bf[np * 2 + 1][1] = t4[3];
            }
#pragma unroll
            for (int mi = 0; mi < 4; mi++)
#pragma unroll
                for (int ni = 0; ni < 4; ni++)
                    mma16816(acc[mi][ni], af[mi], bf[ni]);
        }
        if (more) {
#pragma unroll
            for (int i = 0; i < 4; i++) {
                sts4h(&sA[buf ^ 1][arow[i]][acol[i]], ar[i]);
                sts4h(&sB[buf ^ 1][brow[i]][bcol[i]], br[i]);
            }
        }
        __syncthreads();
        buf ^= 1;
    }

    // epilogue: + b1, gelu, store fp16
    int rb = row0 + wm * 64, cb = col0 + wn * 32;
#pragma unroll
    for (int mi = 0; mi < 4; mi++) {
#pragma unroll
        for (int ni = 0; ni < 4; ni++) {
            int gr = rb + mi * 16 + (lane >> 2);
            int gc = cb + ni * 8 + (lane & 3) * 2;
            float b0 = bias[gc], b1v = bias[gc + 1];
            float v0 = gelu_exact(acc[mi][ni][0] + b0);
            float v1 = gelu_exact(acc[mi][ni][1] + b1v);
            *reinterpret_cast<__half2*>(&g_h[(size_t)gr * HDIM + gc]) = __floats2half2_rn(v0, v1);
            float v2 = gelu_exact(acc[mi][ni][2] + b0);
            float v3 = gelu_exact(acc[mi][ni][3] + b1v);
            *reinterpret_cast<__half2*>(&g_h[(size_t)(gr + 8) * HDIM + gc]) = __floats2half2_rn(v2, v3);
        }
    }
}

// ---------------- GEMM2: eo = h @ W2[e]^T + b2[e] -> fp32 ----------------
// M=128/tile, N=DDIM, K=HDIM.  A fp16 (g_h, contiguous), B fp32 [D,H].
__global__ __launch_bounds__(256) void k_gemm2(
    const float* __restrict__ W2, const float* __restrict__ b2,
    const float* __restrict__ Ws2, const float* __restrict__ bs2) {
    __shared__ __half sA[2][128][40];
    __shared__ __half sB[2][128][40];

    int ty = blockIdx.y;
    int e  = g_tile_expert[ty];
    if (e < 0) return;
    const float* Bsrc; const float* bias;
    if (e == EXP) { Bsrc = Ws2; bias = bs2; }
    else          { Bsrc = W2 + (size_t)e * DDIM * HDIM; bias = b2 + (size_t)e * DDIM; }

    int row0 = ty * 128, col0 = blockIdx.x * 128;
    int tid = threadIdx.x, lane = tid & 31, warp = tid >> 5;
    int wm = warp >> 2, wn = warp & 3;

    // A staging: 2 uint4 slots (8 halves each); B staging: 4 float4 slots
    const __half* abase[2]; int arow[2], acol[2];
    const float*  bbase[4]; int brow[4], bcol[4];
#pragma unroll
    for (int i = 0; i < 2; i++) {
        int lin = tid + i * 256;          // 0..511
        int r = lin >> 2, g8 = lin & 3;   // r:0..127 g8:0..3
        arow[i] = r; acol[i] = g8 * 8;
        abase[i] = g_h + (size_t)(row0 + r) * HDIM + g8 * 8;
    }
#pragma unroll
    for (int i = 0; i < 4; i++) {
        int lin = tid + i * 256;
        int r = lin >> 3, c4 = lin & 7;
        brow[i] = r; bcol[i] = c4 * 4;
        bbase[i] = Bsrc + (size_t)(col0 + r) * HDIM + c4 * 4;
    }

    uint4 ar[2]; float4 br[4];
#pragma unroll
    for (int i = 0; i < 2; i++) ar[i] = *reinterpret_cast<const uint4*>(abase[i]);
#pragma unroll
    for (int i = 0; i < 4; i++) br[i] = *reinterpret_cast<const float4*>(bbase[i]);
#pragma unroll
    for (int i = 0; i < 2; i++)
        *reinterpret_cast<uint4*>(&sA[0][arow[i]][acol[i]]) = ar[i];
#pragma unroll
    for (int i = 0; i < 4; i++)
        sts4h(&sB[0][brow[i]][bcol[i]], br[i]);
    __syncthreads();

    float acc[4][4][4];
#pragma unroll
    for (int mi = 0; mi < 4; mi++)
#pragma unroll
        for (int ni = 0; ni < 4; ni++)
#pragma unroll
            for (int j = 0; j < 4; j++) acc[mi][ni][j] = 0.f;

    int buf = 0;
    for (int kk = 0; kk < HDIM; kk += 32) {
        int nk = kk + 32;
        bool more = (nk < HDIM);
        if (more) {
#pragma unroll
            for (int i = 0; i < 2; i++)
                ar[i] = *reinterpret_cast<const uint4*>(abase[i] + nk);
#pragma unroll
            for (int i = 0; i < 4; i++)
                br[i] = *reinterpret_cast<const float4*>(bbase[i] + nk);
        }
#pragma unroll
        for (int ks = 0; ks < 32; ks += 16) {
            uint32_t af[4][4], bf[4][2];
#pragma unroll
            for (int mi = 0; mi < 4; mi++) {
                int r = wm * 64 + mi * 16 + ((lane >> 3) & 1) * 8 + (lane & 7);
                int c = ks + (lane >> 4) * 8;
                ldsm_x4(af[mi], &sA[buf][r][c]);
            }
#pragma unroll
            for (int np = 0; np < 2; np++) {
                int r = wn * 32 + np * 16 + (lane >> 4) * 8 + (lane & 7);
                int c = ks + ((lane >> 3) & 1) * 8;
                uint32_t t4[4];
                ldsm_x4(t4, &sB[buf][r][c]);
                bf[np * 2][0] = t4[0]; bf[np * 2][1] = t4[1];
                bf[np * 2 + 1][0] = t4[2]; bf[np * 2 + 1][1] = t4[3];
            }
#pragma unroll
            for (int mi = 0; mi < 4; mi++)
#pragma unroll
                for (int ni = 0; ni < 4; ni++)
                    mma16816(acc[mi][ni], af[mi], bf[ni]);
        }
        if (more) {
#pragma unroll
            for (int i = 0; i < 2; i++)
                *reinterpret_cast<uint4*>(&sA[buf ^ 1][arow[i]][acol[i]]) = ar[i];
#pragma unroll
            for (int i = 0; i < 4; i++)
                sts4h(&sB[buf ^ 1][brow[i]][bcol[i]], br[i]);
        }
        __syncthreads();
        buf ^= 1;
    }

    int rb = row0 + wm * 64, cb = col0 + wn * 32;
#pragma unroll
    for (int mi = 0; mi < 4; mi++) {
#pragma unroll
        for (int ni = 0; ni < 4; ni++) {
            int gr = rb + mi * 16 + (lane >> 2);
            int gc = cb + ni * 8 + (lane & 3) * 2;
            float b0 = bias[gc], b1v = bias[gc + 1];
            float2 v01 = make_float2(acc[mi][ni][0] + b0, acc[mi][ni][1] + b1v);
            float2 v23 = make_float2(acc[mi][ni][2] + b0, acc[mi][ni][3] + b1v);
            *reinterpret_cast<float2*>(&g_eo[(size_t)gr * DDIM + gc]) = v01;
            *reinterpret_cast<float2*>(&g_eo[(size_t)(gr + 8) * DDIM + gc]) = v23;
        }
    }
}

// ---------------- combine: out = shared + w0*eo0 + w1*eo1 ----------------
__global__ void k_combine(float* __restrict__ out) {
    int i = blockIdx.x * blockDim.x + threadIdx.x;
    if (i >= T_TOK * DDIM) return;
    int t = i >> 10;
    int d = i & (DDIM - 1);
    float v = g_eo[(size_t)(SHARED_BASE + t) * DDIM + d];
    v += g_top_w[2 * t]     * g_eo[(size_t)g_slot[2 * t]     * DDIM + d];
    v += g_top_w[2 * t + 1] * g_eo[(size_t)g_slot[2 * t + 1] * DDIM + d];
    out[i] = v;
}

// ---------------- launch ----------------
extern "C" void kernel_launch(void* const* d_in, const int* in_sizes, int n_in,
                              void* d_out, int out_size) {
    const float* x    = (const float*)d_in[0];
    const float* Wg   = (const float*)d_in[1];
    const float* bg   = (const float*)d_in[2];
    const float* bias = (const float*)d_in[3];
    const float* W1   = (const float*)d_in[4];
    const float* b1   = (const float*)d_in[5];
    const float* W2   = (const float*)d_in[6];
    const float* b2   = (const float*)d_in[7];
    const float* Ws1  = (const float*)d_in[8];
    const float* bs1  = (const float*)d_in[9];
    const float* Ws2  = (const float*)d_in[10];
    const float* bs2  = (const float*)d_in[11];
    float* out = (float*)d_out;

    k_init<<<(TOTAL_ROWS + 255) / 256, 256>>>();
    k_gate<<<(T_TOK * 32 + 255) / 256, 256>>>(x, Wg, bg, bias);
    k_seg<<<1, 32>>>();
    k_scatter<<<(T_TOK + 255) / 256, 256>>>();
    k_gemm1<<<dim3(HDIM / 128, NTILES), 256>>>(x, W1, b1, Ws1, bs1);
    k_gemm2<<<dim3(DDIM / 128, NTILES), 256>>>(W2, b2, Ws2, bs2);
    k_combine<<<(T_TOK * DDIM + 255) / 256, 256>>>(out);
}

// round 3
// speedup vs baseline: 1.1221x; 1.1221x over previous
#include <cuda_runtime.h>
#include <cuda_fp16.h>
#include <cstdint>

// ---------------- problem constants ----------------
#define T_TOK   2048
#define DDIM    1024
#define EXP     8
#define HDIM    4096
#define ROUTED_CAP  6144          // 4096 selections + per-expert 256-alignment pad
#define SHARED_BASE 6144
#define TOTAL_ROWS  8192
#define MTILE   256
#define NMT     (TOTAL_ROWS / MTILE)    // 32
#define ROUTED_MT (ROUTED_CAP / MTILE)  // 24
#define EW_STRIDE (HDIM * DDIM)

// ---------------- device scratch ----------------
__device__ int   g_cnt[EXP];
__device__ int   g_fill[EXP];
__device__ int   g_segstart[EXP];
__device__ int   g_texp[NMT];
__device__ int   g_row_token[TOTAL_ROWS];
__device__ int   g_top_idx[T_TOK * 2];
__device__ float g_top_w[T_TOK * 2];
__device__ int   g_slot[T_TOK * 2];
__device__ __align__(16) __half g_xh[(size_t)TOTAL_ROWS * DDIM];        // 16.8 MB
__device__ __align__(16) __half g_w1h[(size_t)(EXP + 1) * EW_STRIDE];   // 75.5 MB
__device__ __align__(16) __half g_w2h[(size_t)(EXP + 1) * EW_STRIDE];   // 75.5 MB
__device__ __align__(16) float  g_b1u[(EXP + 1) * HDIM];
__device__ __align__(16) float  g_b2u[(EXP + 1) * DDIM];
__device__ __align__(16) __half g_h[(size_t)TOTAL_ROWS * HDIM];         // 67 MB
__device__ __align__(16) float  g_eo[(size_t)TOTAL_ROWS * DDIM];        // 33.5 MB

// ---------------- helpers ----------------
__device__ __forceinline__ float gelu_exact(float v) {
    return 0.5f * v * (1.0f + erff(v * 0.70710678118654752f));
}

__device__ __forceinline__ uint32_t smem_to_u32(const void* p) {
    uint32_t a;
    asm("{ .reg .u64 t; cvta.to.shared.u64 t, %1; cvt.u32.u64 %0, t; }" : "=r"(a) : "l"(p));
    return a;
}

__device__ __forceinline__ void ldsm_x4(uint32_t* r, uint32_t a) {
    asm volatile("ldmatrix.sync.aligned.m8n8.x4.shared.b16 {%0,%1,%2,%3}, [%4];\n"
                 : "=r"(r[0]), "=r"(r[1]), "=r"(r[2]), "=r"(r[3]) : "r"(a));
}

__device__ __forceinline__ void mma16816(float* c, const uint32_t* a, const uint32_t* b) {
    asm volatile(
        "mma.sync.aligned.m16n8k16.row.col.f32.f16.f16.f32 "
        "{%0,%1,%2,%3}, {%4,%5,%6,%7}, {%8,%9}, {%0,%1,%2,%3};\n"
        : "+f"(c[0]), "+f"(c[1]), "+f"(c[2]), "+f"(c[3])
        : "r"(a[0]), "r"(a[1]), "r"(a[2]), "r"(a[3]), "r"(b[0]), "r"(b[1]));
}

#define CP_ASYNC16(dst_u32, src_ptr) \
    asm volatile("cp.async.cg.shared.global [%0], [%1], 16;" :: "r"(dst_u32), "l"(src_ptr) : "memory")
#define CP_COMMIT() asm volatile("cp.async.commit_group;" ::: "memory")
#define CP_WAIT2()  asm volatile("cp.async.wait_group 2;" ::: "memory")

// ---------------- routing kernels ----------------
__global__ void k_init() {
    int i = blockIdx.x * blockDim.x + threadIdx.x;
    if (i < TOTAL_ROWS)
        g_row_token[i] = (i >= SHARED_BASE) ? (i - SHARED_BASE) : -1;
    if (i < EXP) { g_cnt[i] = 0; g_fill[i] = 0; }
}

__global__ void k_gate(const float* __restrict__ x, const float* __restrict__ Wg,
                       const float* __restrict__ bg, const float* __restrict__ bias) {
    int gwarp = (blockIdx.x * blockDim.x + threadIdx.x) >> 5;
    int lane  = threadIdx.x & 31;
    if (gwarp >= T_TOK) return;
    const float* xr = x + (size_t)gwarp * DDIM;
    float xs[32];
#pragma unroll
    for (int j = 0; j < 32; j++) xs[j] = xr[lane + 32 * j];
    float s[EXP];
#pragma unroll
    for (int e = 0; e < EXP; e++) {
        const float* wr = Wg + e * DDIM;
        float a = 0.f;
#pragma unroll
        for (int j = 0; j < 32; j++) a += xs[j] * wr[lane + 32 * j];
#pragma unroll
        for (int o = 16; o > 0; o >>= 1) a += __shfl_xor_sync(0xffffffffu, a, o);
        s[e] = 1.0f / (1.0f + expf(-(a + bg[e] + bias[e])));
    }
    if (lane == 0) {
        int i0 = 0; float v0 = s[0];
#pragma unroll
        for (int e = 1; e < EXP; e++) if (s[e] > v0) { v0 = s[e]; i0 = e; }
        int i1 = -1; float v1 = -1e30f;
#pragma unroll
        for (int e = 0; e < EXP; e++) if (e != i0 && s[e] > v1) { v1 = s[e]; i1 = e; }
        g_top_idx[2 * gwarp]     = i0; g_top_w[2 * gwarp]     = v0;
        g_top_idx[2 * gwarp + 1] = i1; g_top_w[2 * gwarp + 1] = v1;
        atomicAdd(&g_cnt[i0], 1);
        atomicAdd(&g_cnt[i1], 1);
    }
}

__global__ void k_seg() {
    if (threadIdx.x == 0 && blockIdx.x == 0) {
        int off = 0;
        for (int e = 0; e < EXP; e++) {
            g_segstart[e] = off;
            int tiles = (g_cnt[e] + 255) >> 8;
            for (int i = 0; i < tiles; i++) g_texp[(off >> 8) + i] = e;
            off += tiles << 8;
        }
        for (int t = off >> 8; t < ROUTED_MT; t++) g_texp[t] = -1;
        for (int t = ROUTED_MT; t < NMT; t++)      g_texp[t] = EXP;  // shared expert
    }
}

__global__ void k_scatter() {
    int t = blockIdx.x * blockDim.x + threadIdx.x;
    if (t >= T_TOK) return;
#pragma unroll
    for (int k = 0; k < 2; k++) {
        int e = g_top_idx[2 * t + k];
        int pos = atomicAdd(&g_fill[e], 1);
        int row = g_segstart[e] + pos;
        g_slot[2 * t + k] = row;
        g_row_token[row]  = t;
    }
}

// scatter + convert x rows into padded fp16 layout (zeros for padding rows)
__global__ void k_xh(const float* __restrict__ x) {
    int r = blockIdx.x;
    int c = threadIdx.x * 8;
    int tok = g_row_token[r];
    __half* dst = g_xh + (size_t)r * DDIM + c;
    if (tok < 0) {
        *reinterpret_cast<uint4*>(dst) = make_uint4(0, 0, 0, 0);
        return;
    }
    const float* src = x + (size_t)tok * DDIM + c;
    float4 a = *reinterpret_cast<const float4*>(src);
    float4 b = *reinterpret_cast<const float4*>(src + 4);
    __half2 h0 = __floats2half2_rn(a.x, a.y), h1 = __floats2half2_rn(a.z, a.w);
    __half2 h2 = __floats2half2_rn(b.x, b.y), h3 = __floats2half2_rn(b.z, b.w);
    uint4 o;
    o.x = *reinterpret_cast<uint32_t*>(&h0); o.y = *reinterpret_cast<uint32_t*>(&h1);
    o.z = *reinterpret_cast<uint32_t*>(&h2); o.w = *reinterpret_cast<uint32_t*>(&h3);
    *reinterpret_cast<uint4*>(dst) = o;
}

// fp32 -> fp16 bulk convert
__global__ void k_cvt(const float* __restrict__ s, __half* __restrict__ d, int n) {
    int i = (blockIdx.x * blockDim.x + threadIdx.x) * 8;
    if (i >= n) return;
    float4 a = *reinterpret_cast<const float4*>(s + i);
    float4 b = *reinterpret_cast<const float4*>(s + i + 4);
    __half2 h0 = __floats2half2_rn(a.x, a.y), h1 = __floats2half2_rn(a.z, a.w);
    __half2 h2 = __floats2half2_rn(b.x, b.y), h3 = __floats2half2_rn(b.z, b.w);
    uint4 o;
    o.x = *reinterpret_cast<uint32_t*>(&h0); o.y = *reinterpret_cast<uint32_t*>(&h1);
    o.z = *reinterpret_cast<uint32_t*>(&h2); o.w = *reinterpret_cast<uint32_t*>(&h3);
    *reinterpret_cast<uint4*>(d + i) = o;
}

__global__ void k_bias(const float* __restrict__ b1, const float* __restrict__ bs1,
                       const float* __restrict__ b2, const float* __restrict__ bs2) {
    int i = blockIdx.x * blockDim.x + threadIdx.x;
    if (i < EXP * HDIM) g_b1u[i] = b1[i];
    if (i < HDIM)       g_b1u[EXP * HDIM + i] = bs1[i];
    if (i < EXP * DDIM) g_b2u[i] = b2[i];
    if (i < DDIM)       g_b2u[EXP * DDIM + i] = bs2[i];
}

// ---------------- fp16 grouped GEMM (mma.sync, 4-stage cp.async) ----------------
// Tile 256(M) x 128(N), K-chunk 32. 8 warps: 4(M) x 2(N), 64x64 per warp.
// smem per stage: A 256x40 halves (20480B) + B 128x40 halves (10240B) = 30720B.
// 4 stages = 122880B dynamic smem.
#define STG   4
#define STGB  30720
#define A_PAD 40

template <int KDIM, bool DOGELU>
__global__ __launch_bounds__(256, 1) void k_gemm(
    const __half* __restrict__ A,      // [TOTAL_ROWS, KDIM] fp16
    const __half* __restrict__ W,      // [(EXP+1), NTOT, KDIM] fp16
    const float*  __restrict__ biasU,  // [(EXP+1), NTOT]
    int NTOT)
{
    constexpr int KT = KDIM / 32;
    extern __shared__ char smem[];
    const uint32_t sb = smem_to_u32(smem);

    const int mt = blockIdx.y;
    const int e  = g_texp[mt];
    if (e < 0) return;
    const int row0 = mt * MTILE;
    const int col0 = blockIdx.x * 128;
    const __half* Wb = W + (size_t)e * NTOT * KDIM;

    const int tid = threadIdx.x, lane = tid & 31, warp = tid >> 5;
    const int wm = warp >> 1, wn = warp & 1;

    // per-thread cp.async assignments
    const __half* asrc[4]; uint32_t aoff[4];
    const __half* bsrc[2]; uint32_t boff[2];
#pragma unroll
    for (int i = 0; i < 4; i++) {
        int l = tid + i * 256;            // 0..1023
        int r = l >> 2, c8 = l & 3;       // r 0..255, 4 x 16B chunks
        asrc[i] = A + (size_t)(row0 + r) * KDIM + c8 * 8;
        aoff[i] = r * (A_PAD * 2) + c8 * 16;
    }
#pragma unroll
    for (int i = 0; i < 2; i++) {
        int l = tid + i * 256;            // 0..511
        int r = l >> 2, c8 = l & 3;       // r 0..127
        bsrc[i] = Wb + (size_t)(col0 + r) * KDIM + c8 * 8;
        boff[i] = 20480 + r * (A_PAD * 2) + c8 * 16;
    }

    auto LOAD = [&](int st, int ch) {
        uint32_t base = sb + st * STGB;
        int koff = ch * 32;
#pragma unroll
        for (int i = 0; i < 4; i++) CP_ASYNC16(base + aoff[i], asrc[i] + koff);
#pragma unroll
        for (int i = 0; i < 2; i++) CP_ASYNC16(base + boff[i], bsrc[i] + koff);
    };

    float acc[4][8][4];
#pragma unroll
    for (int mi = 0; mi < 4; mi++)
#pragma unroll
        for (int ni = 0; ni < 8; ni++)
#pragma unroll
            for (int j = 0; j < 4; j++) acc[mi][ni][j] = 0.f;

    // prologue: 3 chunks in flight
#pragma unroll
    for (int c = 0; c < STG - 1; c++) { LOAD(c, c); CP_COMMIT(); }

    // precomputed ldmatrix smem addrs (stage-relative)
    uint32_t a_ld[4], b_ld[4];
#pragma unroll
    for (int mi = 0; mi < 4; mi++) {
        int r = wm * 64 + mi * 16 + ((lane >> 3) & 1) * 8 + (lane & 7);
        int c = (lane >> 4) * 8;
        a_ld[mi] = sb + r * (A_PAD * 2) + c * 2;
    }
#pragma unroll
    for (int np = 0; np < 4; np++) {
        int r = wn * 64 + np * 16 + (lane >> 4) * 8 + (lane & 7);
        int c = ((lane >> 3) & 1) * 8;
        b_ld[np] = sb + 20480 + r * (A_PAD * 2) + c * 2;
    }

#pragma unroll 1
    for (int i = 0; i < KT; i++) {
        CP_WAIT2();
        __syncthreads();
        int j = i + STG - 1;
        if (j < KT) LOAD(j & (STG - 1), j);
        CP_COMMIT();

        uint32_t stoff = (i & (STG - 1)) * STGB;
#pragma unroll
        for (int ks = 0; ks < 32; ks += 16) {
            uint32_t af[4][4], bf[8][2];
#pragma unroll
            for (int mi = 0; mi < 4; mi++) ldsm_x4(af[mi], a_ld[mi] + stoff + ks * 2);
#pragma unroll
            for (int np = 0; np < 4; np++) {
                uint32_t t4[4];
                ldsm_x4(t4, b_ld[np] + stoff + ks * 2);
                bf[np * 2][0] = t4[0]; bf[np * 2][1] = t4[1];
                bf[np * 2 + 1][0] = t4[2]; bf[np * 2 + 1][1] = t4[3];
            }
#pragma unroll
            for (int mi = 0; mi < 4; mi++)
#pragma unroll
                for (int ni = 0; ni < 8; ni++)
                    mma16816(acc[mi][ni], af[mi], bf[ni]);
        }
    }

    // epilogue
    const float* bias = biasU + e * NTOT;
#pragma unroll
    for (int mi = 0; mi < 4; mi++) {
#pragma unroll
        for (int ni = 0; ni < 8; ni++) {
            int gr = row0 + wm * 64 + mi * 16 + (lane >> 2);
            int gc = col0 + wn * 64 + ni * 8 + (lane & 3) * 2;
            float b0 = bias[gc], b1v = bias[gc + 1];
            if (DOGELU) {
                float v0 = gelu_exact(acc[mi][ni][0] + b0);
                float v1 = gelu_exact(acc[mi][ni][1] + b1v);
                *reinterpret_cast<__half2*>(&g_h[(size_t)gr * HDIM + gc]) =
                    __floats2half2_rn(v0, v1);
                float v2 = gelu_exact(acc[mi][ni][2] + b0);
                float v3 = gelu_exact(acc[mi][ni][3] + b1v);
                *reinterpret_cast<__half2*>(&g_h[(size_t)(gr + 8) * HDIM + gc]) =
                    __floats2half2_rn(v2, v3);
            } else {
                float2 v01 = make_float2(acc[mi][ni][0] + b0, acc[mi][ni][1] + b1v);
                float2 v23 = make_float2(acc[mi][ni][2] + b0, acc[mi][ni][3] + b1v);
                *reinterpret_cast<float2*>(&g_eo[(size_t)gr * DDIM + gc]) = v01;
                *reinterpret_cast<float2*>(&g_eo[(size_t)(gr + 8) * DDIM + gc]) = v23;
            }
        }
    }
}

// ---------------- combine ----------------
__global__ void k_combine(float* __restrict__ out) {
    int i = blockIdx.x * blockDim.x + threadIdx.x;
    if (i >= T_TOK * DDIM) return;
    int t = i >> 10;
    int d = i & (DDIM - 1);
    float v = g_eo[(size_t)(SHARED_BASE + t) * DDIM + d];
    v += g_top_w[2 * t]     * g_eo[(size_t)g_slot[2 * t]     * DDIM + d];
    v += g_top_w[2 * t + 1] * g_eo[(size_t)g_slot[2 * t + 1] * DDIM + d];
    out[i] = v;
}

// ---------------- launch ----------------
#define GEMM_SMEM (STG * STGB)   // 122880

extern "C" void kernel_launch(void* const* d_in, const int* in_sizes, int n_in,
                              void* d_out, int out_size) {
    const float* x    = (const float*)d_in[0];
    const float* Wg   = (const float*)d_in[1];
    const float* bg   = (const float*)d_in[2];
    const float* bias = (const float*)d_in[3];
    const float* W1   = (const float*)d_in[4];
    const float* b1   = (const float*)d_in[5];
    const float* W2   = (const float*)d_in[6];
    const float* b2   = (const float*)d_in[7];
    const float* Ws1  = (const float*)d_in[8];
    const float* bs1  = (const float*)d_in[9];
    const float* Ws2  = (const float*)d_in[10];
    const float* bs2  = (const float*)d_in[11];
    float* out = (float*)d_out;

    static bool attr_set = false;
    if (!attr_set) {
        cudaFuncSetAttribute(k_gemm<DDIM, true>,
                             cudaFuncAttributeMaxDynamicSharedMemorySize, GEMM_SMEM);
        cudaFuncSetAttribute(k_gemm<HDIM, false>,
                             cudaFuncAttributeMaxDynamicSharedMemorySize, GEMM_SMEM);
        attr_set = true;
    }

    __half* w1h; __half* w2h; __half* xh; __half* hh; float* b1u; float* b2u;
    cudaGetSymbolAddress((void**)&w1h, g_w1h);
    cudaGetSymbolAddress((void**)&w2h, g_w2h);
    cudaGetSymbolAddress((void**)&xh,  g_xh);
    cudaGetSymbolAddress((void**)&hh,  g_h);
    cudaGetSymbolAddress((void**)&b1u, g_b1u);
    cudaGetSymbolAddress((void**)&b2u, g_b2u);

    k_init<<<TOTAL_ROWS / 256, 256>>>();
    k_gate<<<T_TOK * 32 / 256, 256>>>(x, Wg, bg, bias);
    k_seg<<<1, 32>>>();
    k_scatter<<<T_TOK / 256, 256>>>();
    k_xh<<<TOTAL_ROWS, 128>>>(x);
    k_cvt<<<EXP * EW_STRIDE / 8 / 256, 256>>>(W1,  w1h,                           EXP * EW_STRIDE);
    k_cvt<<<EW_STRIDE / 8 / 256,       256>>>(Ws1, w1h + (size_t)EXP * EW_STRIDE, EW_STRIDE);
    k_cvt<<<EXP * EW_STRIDE / 8 / 256, 256>>>(W2,  w2h,                           EXP * EW_STRIDE);
    k_cvt<<<EW_STRIDE / 8 / 256,       256>>>(Ws2, w2h + (size_t)EXP * EW_STRIDE, EW_STRIDE);
    k_bias<<<EXP * HDIM / 256, 256>>>(b1, bs1, b2, bs2);

    k_gemm<DDIM, true ><<<dim3(HDIM / 128, NMT), 256, GEMM_SMEM>>>(xh, w1h, b1u, HDIM);
    k_gemm<HDIM, false><<<dim3(DDIM / 128, NMT), 256, GEMM_SMEM>>>(hh, w2h, b2u, DDIM);

    k_combine<<<T_TOK * DDIM / 256, 256>>>(out);
}